// round 1
// baseline (speedup 1.0000x reference)
#include <cuda_runtime.h>
#include <cstdint>

// Problem constants (fixed shapes for this problem instance)
#define NNODES 8192
#define NEDGES 262144
#define DIN    512
#define DH     256
#define ALPHA  0.1520f
#define BETA   0.7900f

// ---------------- scratch (device globals; no allocation allowed) ----------
__device__ float g_deg [NNODES];
__device__ float g_dinv[NNODES];
__device__ float g_Y1  [NNODES * DH];   // X @ W1
__device__ float g_P1  [NNODES * DH];   // edge-aggregated Y1 (atomic target)
__device__ float g_Y2  [NNODES * 2];    // relu(prop1+b1) @ W2
__device__ float g_eacc[NNODES * 2];    // edge-aggregated Y2 (atomic target)
__device__ float g_ex  [NNODES];
__device__ float g_ey  [NNODES];

// ---------------- zero accumulators (must run every launch: graph replays) --
__global__ void zero_kernel() {
    int idx = blockIdx.x * blockDim.x + threadIdx.x;
    float4 z = make_float4(0.f, 0.f, 0.f, 0.f);
    if (idx < NNODES * DH / 4) ((float4*)g_P1)[idx] = z;
    if (idx < NNODES * 2 / 4)  ((float4*)g_eacc)[idx] = z;
    if (idx < NNODES / 4)      ((float4*)g_deg)[idx] = z;
}

// ---------------- degree (in-degree of dst) --------------------------------
__global__ void deg_kernel(const int* __restrict__ dst) {
    int e = blockIdx.x * blockDim.x + threadIdx.x;
    if (e < NEDGES) atomicAdd(&g_deg[dst[e]], 1.0f);
}

__global__ void dinv_kernel() {
    int i = blockIdx.x * blockDim.x + threadIdx.x;
    if (i < NNODES) g_dinv[i] = rsqrtf(g_deg[i] + 1.0f);
}

// ---------------- GEMM1: Y1[8192,256] = X[8192,512] @ W1[512,256] ----------
// BM=64 BN=64 BK=32, 256 threads, 4x4 per thread.
__global__ __launch_bounds__(256) void gemm1_kernel(const float* __restrict__ X,
                                                    const float* __restrict__ W1) {
    __shared__ float As[32][64];   // [k][m]
    __shared__ float Bs[32][64];   // [k][n]
    const int bm = blockIdx.y * 64;
    const int bn = blockIdx.x * 64;
    const int tid = threadIdx.x;
    const int tx = tid % 16;       // n-group
    const int ty = tid / 16;       // m-group

    float acc[4][4];
#pragma unroll
    for (int a = 0; a < 4; a++)
#pragma unroll
        for (int b = 0; b < 4; b++) acc[a][b] = 0.f;

    for (int k0 = 0; k0 < DIN; k0 += 32) {
        // load A tile (64 x 32), store transposed into As[k][m]
#pragma unroll
        for (int it = 0; it < 2; ++it) {
            int r = (tid >> 3) + it * 32;        // 0..63
            int c = (tid & 7) << 2;              // 0..28
            float4 v = *(const float4*)&X[(size_t)(bm + r) * DIN + k0 + c];
            As[c + 0][r] = v.x; As[c + 1][r] = v.y;
            As[c + 2][r] = v.z; As[c + 3][r] = v.w;
        }
        // load B tile (32 x 64) into Bs[k][n]
#pragma unroll
        for (int it = 0; it < 2; ++it) {
            int r = (tid >> 4) + it * 16;        // 0..31
            int c = (tid & 15) << 2;             // 0..60
            *(float4*)&Bs[r][c] = *(const float4*)&W1[(size_t)(k0 + r) * DH + bn + c];
        }
        __syncthreads();
#pragma unroll
        for (int k = 0; k < 32; ++k) {
            float a4[4], b4[4];
            *(float4*)a4 = *(const float4*)&As[k][ty << 2];
            *(float4*)b4 = *(const float4*)&Bs[k][tx << 2];
#pragma unroll
            for (int m = 0; m < 4; m++)
#pragma unroll
                for (int n = 0; n < 4; n++)
                    acc[m][n] = fmaf(a4[m], b4[n], acc[m][n]);
        }
        __syncthreads();
    }
#pragma unroll
    for (int m = 0; m < 4; m++) {
        float4 v = make_float4(acc[m][0], acc[m][1], acc[m][2], acc[m][3]);
        *(float4*)&g_Y1[(size_t)(bm + (ty << 2) + m) * DH + bn + (tx << 2)] = v;
    }
}

// ---------------- prop1: P1[dst] += Y1[src] * (dinv[src]*dinv[dst]) --------
// one warp per edge; 2 x red.global.add.v4.f32 per lane (256 floats/edge)
__global__ __launch_bounds__(256) void prop1_kernel(const int* __restrict__ src,
                                                    const int* __restrict__ dst) {
    int w = (blockIdx.x * blockDim.x + threadIdx.x) >> 5;
    int lane = threadIdx.x & 31;
    if (w >= NEDGES) return;
    int s = __ldg(&src[w]);
    int d = __ldg(&dst[w]);
    float nrm = g_dinv[s] * g_dinv[d];
    const float4* yrow = (const float4*)(g_Y1 + (size_t)s * DH);
    float* prow = g_P1 + (size_t)d * DH;
#pragma unroll
    for (int it = 0; it < 2; ++it) {
        int c = lane + it * 32;                  // float4 index 0..63
        float4 v = __ldg(&yrow[c]);
        float* p = prow + (c << 2);
        asm volatile("red.global.add.v4.f32 [%0], {%1,%2,%3,%4};"
                     :: "l"(p), "f"(v.x * nrm), "f"(v.y * nrm),
                        "f"(v.z * nrm), "f"(v.w * nrm) : "memory");
    }
}

// ---------------- node fuse: h = relu(P1 + Y1*dinv^2 + b1); Y2 = h @ W2 ----
// one warp per node
__global__ __launch_bounds__(256) void node2_kernel(const float* __restrict__ b1,
                                                    const float* __restrict__ W2) {
    int node = (blockIdx.x * blockDim.x + threadIdx.x) >> 5;
    int lane = threadIdx.x & 31;
    if (node >= NNODES) return;
    float di = g_dinv[node];
    float di2 = di * di;
    const float* prow = g_P1 + (size_t)node * DH;
    const float* yrow = g_Y1 + (size_t)node * DH;
    const float2* w2 = (const float2*)W2;
    float s0 = 0.f, s1 = 0.f;
#pragma unroll
    for (int j = 0; j < DH / 32; ++j) {
        int d = lane + j * 32;
        float h = prow[d] + yrow[d] * di2 + b1[d];
        h = fmaxf(h, 0.f);
        float2 w = __ldg(&w2[d]);
        s0 = fmaf(h, w.x, s0);
        s1 = fmaf(h, w.y, s1);
    }
#pragma unroll
    for (int off = 16; off > 0; off >>= 1) {
        s0 += __shfl_down_sync(0xffffffffu, s0, off);
        s1 += __shfl_down_sync(0xffffffffu, s1, off);
    }
    if (lane == 0) {
        g_Y2[node * 2 + 0] = s0;
        g_Y2[node * 2 + 1] = s1;
    }
}

// ---------------- prop2: eacc[dst] += Y2[src] * norm (2-dim) ---------------
__global__ void prop2_kernel(const int* __restrict__ src, const int* __restrict__ dst) {
    int e = blockIdx.x * blockDim.x + threadIdx.x;
    if (e >= NEDGES) return;
    int s = src[e], d = dst[e];
    float nrm = g_dinv[s] * g_dinv[d];
    float2 y = ((const float2*)g_Y2)[s];
    float* p = g_eacc + (size_t)d * 2;
    asm volatile("red.global.add.v2.f32 [%0], {%1,%2};"
                 :: "l"(p), "f"(y.x * nrm), "f"(y.y * nrm) : "memory");
}

// ---------------- finalize emb: + self loop + b2; write emb to output ------
__global__ void fin_kernel(const float* __restrict__ b2, float* __restrict__ out) {
    int i = blockIdx.x * blockDim.x + threadIdx.x;
    if (i >= NNODES) return;
    float di = g_dinv[i];
    float di2 = di * di;
    float2 y = ((const float2*)g_Y2)[i];
    float ex = g_eacc[2 * i + 0] + y.x * di2 + b2[0];
    float ey = g_eacc[2 * i + 1] + y.y * di2 + b2[1];
    g_ex[i] = ex;
    g_ey[i] = ey;
    out[2 * i + 0] = ex;
    out[2 * i + 1] = ey;
}

// ---------------- q[i,j] = 1/(1 + alpha * (d2)^beta) -----------------------
__device__ __forceinline__ float qval(float dx, float dy) {
    float d2 = fmaf(dx, dx, dy * dy);
    float pw = __powf(d2, BETA);                  // LG2 + FMUL + EX2 (MUFU)
    float q  = __fdividef(1.0f, fmaf(ALPHA, pw, 1.0f));  // MUFU RCP
    return d2 > 0.0f ? q : 1.0f;
}

// block: 256 threads; tile = 8 rows x 128 cols; thread = 1 row x 4 cols
__global__ __launch_bounds__(256) void q_kernel(float* __restrict__ qout) {
    int i = blockIdx.y * 8 + (threadIdx.x >> 5);
    int j = (blockIdx.x << 7) + ((threadIdx.x & 31) << 2);
    float xi = g_ex[i];
    float yi = g_ey[i];
    float4 xj = *(const float4*)&g_ex[j];
    float4 yj = *(const float4*)&g_ey[j];
    float4 r;
    r.x = qval(xi - xj.x, yi - yj.x);
    r.y = qval(xi - xj.y, yi - yj.y);
    r.z = qval(xi - xj.z, yi - yj.z);
    r.w = qval(xi - xj.w, yi - yj.w);
    *(float4*)&qout[(size_t)i * NNODES + j] = r;
}

// ---------------------------------------------------------------------------
extern "C" void kernel_launch(void* const* d_in, const int* in_sizes, int n_in,
                              void* d_out, int out_size) {
    const float* X  = (const float*)d_in[0];   // [8192,512]
    const int*   ei = (const int*)  d_in[1];   // [2,262144]
    const float* W1 = (const float*)d_in[2];   // [512,256]
    const float* b1 = (const float*)d_in[3];   // [256]
    const float* W2 = (const float*)d_in[4];   // [256,2]
    const float* b2 = (const float*)d_in[5];   // [2]
    float* out = (float*)d_out;                // emb (16384) then q (8192*8192)
    (void)in_sizes; (void)n_in; (void)out_size;

    const int* src = ei;
    const int* dst = ei + NEDGES;

    zero_kernel<<<(NNODES * DH / 4 + 255) / 256, 256>>>();
    deg_kernel<<<NEDGES / 256, 256>>>(dst);
    dinv_kernel<<<NNODES / 256, 256>>>();
    gemm1_kernel<<<dim3(DH / 64, NNODES / 64), 256>>>(X, W1);
    prop1_kernel<<<NEDGES * 32 / 256, 256>>>(src, dst);
    node2_kernel<<<NNODES * 32 / 256, 256>>>(b1, W2);
    prop2_kernel<<<NEDGES / 256, 256>>>(src, dst);
    fin_kernel<<<NNODES / 256, 256>>>(b2, out);
    q_kernel<<<dim3(NNODES / 128, NNODES / 8), 256>>>(out + NNODES * 2);
}